// round 4
// baseline (speedup 1.0000x reference)
#include <cuda_runtime.h>

#define BN 1024
#define CN 128
#define DN 16
#define SN 4
#define K3C 23
#define K2C 5
#define K1C 2

// ---------------- scratch (no allocations allowed) ----------------
__device__ float g_uw3[(size_t)SN * CN * 1024 * 16]; // [e][c][m][l], m = oc*256+i*16+j  (32MB)
__device__ float g_uw2[(size_t)SN * CN * 1024];      // [e][c][m]
__device__ float g_uw1[(size_t)SN * CN * 64];        // [e][c][oc*16+i]
__device__ int   g_sorted[BN];
__device__ int   g_off[SN + 1];
__device__ float g_y[(size_t)BN * CN * 4];           // [b][c][oc]

// ---------------- kernel 1: UW3[e,c,m,l] = sum_k u3[.]*w3[br,e,k,c] ----------------
// grid (128 ml-tiles, 2 c-halves, 4 species), 128 threads
__global__ void k_uw3(const float* __restrict__ u3_0, const float* __restrict__ u3_1,
                      const float* __restrict__ w3) {
    __shared__ float s_w3[2 * K3C * CN]; // [br][k][c], 5888 floats
    const int tid = threadIdx.x;
    const int ml  = blockIdx.x * 128 + tid;      // 0..16383
    const int c0  = blockIdx.y * 64;
    const int e   = blockIdx.z;
    const int l = ml & 15, m = ml >> 4;
    const int j = m & 15, i = (m >> 4) & 15, oc = m >> 8;
    const int br = (oc > 0) ? 1 : 0;

    const float* up = (oc == 0)
        ? (u3_0 + ((i * 16 + j) * 16 + l) * K3C)
        : (u3_1 + ((((oc - 1) * 16 + i) * 16 + j) * 16 + l) * K3C);
    float u3r[K3C];
#pragma unroll
    for (int k = 0; k < K3C; k++) u3r[k] = up[k];

    for (int idx = tid; idx < 2 * K3C * CN; idx += 128) {
        int brr = idx / (K3C * 128);
        int rem = idx - brr * (K3C * 128);
        int k = rem >> 7, cc = rem & 127;
        s_w3[idx] = w3[(((size_t)(brr * 4 + e) * K3C + k) * 128) + cc];
    }
    __syncthreads();
    const float* wp = s_w3 + br * (K3C * 128);
    float* outp = g_uw3 + ((size_t)e * 128) * 16384 + ml;
    for (int c = c0; c < c0 + 64; c += 4) {
        float a0 = 0.f, a1 = 0.f, a2 = 0.f, a3 = 0.f;
#pragma unroll
        for (int k = 0; k < K3C; k++) {
            float4 w = *(const float4*)(wp + k * 128 + c);
            a0 = fmaf(u3r[k], w.x, a0);
            a1 = fmaf(u3r[k], w.y, a1);
            a2 = fmaf(u3r[k], w.z, a2);
            a3 = fmaf(u3r[k], w.w, a3);
        }
        outp[(size_t)(c + 0) * 16384] = a0;
        outp[(size_t)(c + 1) * 16384] = a1;
        outp[(size_t)(c + 2) * 16384] = a2;
        outp[(size_t)(c + 3) * 16384] = a3;
    }
}

// ---------------- kernel 2: UW2 / UW1 folds ----------------
// grid 512 (e*128+c), 128 threads
__global__ void k_uw21(const float* __restrict__ u2_0, const float* __restrict__ u2_1,
                       const float* __restrict__ u1_0, const float* __restrict__ u1_1,
                       const float* __restrict__ w2, const float* __restrict__ w1) {
    const int ec = blockIdx.x;
    const int e = ec >> 7, c = ec & 127;
    const int tid = threadIdx.x;
    for (int m = tid; m < 1024; m += 128) {
        int j = m & 15, i = (m >> 4) & 15, oc = m >> 8;
        int br = (oc > 0) ? 1 : 0;
        int o1 = br ? (oc - 1) : 0;
        const float* up = br ? (u2_1 + ((o1 * 16 + i) * 16 + j) * K2C)
                             : (u2_0 + (i * 16 + j) * K2C);
        float acc = 0.f;
#pragma unroll
        for (int k = 0; k < K2C; k++)
            acc = fmaf(up[k], w2[((size_t)((br * 4 + e) * K2C + k)) * 128 + c], acc);
        g_uw2[(size_t)ec * 1024 + m] = acc;
    }
    if (tid < 64) {
        int m = tid;
        int i = m & 15, oc = m >> 4;
        int br = (oc > 0) ? 1 : 0;
        int o1 = br ? (oc - 1) : 0;
        const float* up = br ? (u1_1 + (o1 * 16 + i) * K1C) : (u1_0 + i * K1C);
        float acc = 0.f;
#pragma unroll
        for (int k = 0; k < K1C; k++)
            acc = fmaf(up[k], w1[((size_t)((br * 4 + e) * K1C + k)) * 128 + c], acc);
        g_uw1[(size_t)ec * 64 + m] = acc;
    }
}

// ---------------- kernel 3: counting sort by species ----------------
__global__ void k_sort(const int* __restrict__ species) {
    __shared__ int cnt[SN], cur[SN], off[SN + 1];
    const int tid = threadIdx.x; // 1024
    if (tid < SN) { cnt[tid] = 0; cur[tid] = 0; }
    __syncthreads();
    int s = species[tid];
    atomicAdd(&cnt[s], 1);
    __syncthreads();
    if (tid == 0) {
        off[0] = 0;
        for (int e = 0; e < SN; e++) off[e + 1] = off[e] + cnt[e];
        for (int e = 0; e <= SN; e++) g_off[e] = off[e];
    }
    __syncthreads();
    int pos = off[s] + atomicAdd(&cur[s], 1);
    g_sorted[pos] = tid;
}

// ---------------- kernel 4: main polynomial contraction ----------------
// grid (c=128, e=4, oc=4), 128 threads, 2 nodes/thread, static smem ~17.4KB
#define TM2 128
__global__ __launch_bounds__(TM2, 5) void k_main2(const float* __restrict__ xg) {
    __shared__ float sUW3[4096]; // 16KB: UW3[e,c,oc] slice, [i*16+j][l]
    __shared__ float sUW2[256];  // [i][j]
    __shared__ float sUW1[16];   // [i]

    const int c = blockIdx.x, e = blockIdx.y, oc = blockIdx.z;
    const int tid = threadIdx.x;
    const size_t ec = (size_t)(e * 128 + c);

    {
        const float4* g3 = (const float4*)(g_uw3 + ec * 16384 + (size_t)oc * 4096);
        float4* s3 = (float4*)sUW3;
#pragma unroll
        for (int q = 0; q < 8; q++) s3[tid + q * 128] = g3[tid + q * 128];
        if (tid < 64) ((float4*)sUW2)[tid] = ((const float4*)(g_uw2 + ec * 1024 + oc * 256))[tid];
        if (tid < 4)  ((float4*)sUW1)[tid] = ((const float4*)(g_uw1 + ec * 64 + oc * 16))[tid];
    }
    const int lo = g_off[e], hi = g_off[e + 1];
    __syncthreads();

    for (int base = lo; base < hi; base += 2 * TM2) {
        const int t0 = base + tid;
        const int t1 = t0 + TM2;
        if (t0 >= hi) break;
        const bool v1 = (t1 < hi);
        const int b0 = g_sorted[t0];
        const int b1 = v1 ? g_sorted[t1] : b0;

        float x0[16], x1[16];
        {
            const float4* p0 = (const float4*)(xg + ((size_t)b0 * 128 + c) * 16);
            const float4* p1 = (const float4*)(xg + ((size_t)b1 * 128 + c) * 16);
#pragma unroll
            for (int q = 0; q < 4; q++) {
                float4 a = p0[q];
                x0[4 * q + 0] = a.x; x0[4 * q + 1] = a.y; x0[4 * q + 2] = a.z; x0[4 * q + 3] = a.w;
                float4 b = p1[q];
                x1[4 * q + 0] = b.x; x1[4 * q + 1] = b.y; x1[4 * q + 2] = b.z; x1[4 * q + 3] = b.w;
            }
        }

        float yo0 = 0.f, yo1 = 0.f;
#pragma unroll 1
        for (int i = 0; i < 16; i++) {
            const float* r3 = sUW3 + i * 256;
            const float* r2 = sUW2 + i * 16;
            float a00 = 0.f, a01 = 0.f, a02 = 0.f, a03 = 0.f;
            float a10 = 0.f, a11 = 0.f, a12 = 0.f, a13 = 0.f;
#pragma unroll
            for (int j = 0; j < 16; j++) {
                const float4* p = (const float4*)(r3 + j * 16);
                const float4 A = p[0], B = p[1], C4 = p[2], D4 = p[3];
                const float u = r2[j];            // broadcast scalar LDS
                // node 0: 4 independent chains
                float s0 = fmaf(A.x, x0[0], u);
                float s1 = A.y * x0[1];
                float s2 = A.z * x0[2];
                float s3 = A.w * x0[3];
                s0 = fmaf(B.x,  x0[4],  s0);
                s1 = fmaf(B.y,  x0[5],  s1);
                s2 = fmaf(B.z,  x0[6],  s2);
                s3 = fmaf(B.w,  x0[7],  s3);
                s0 = fmaf(C4.x, x0[8],  s0);
                s1 = fmaf(C4.y, x0[9],  s1);
                s2 = fmaf(C4.z, x0[10], s2);
                s3 = fmaf(C4.w, x0[11], s3);
                s0 = fmaf(D4.x, x0[12], s0);
                s1 = fmaf(D4.y, x0[13], s1);
                s2 = fmaf(D4.z, x0[14], s2);
                s3 = fmaf(D4.w, x0[15], s3);
                const float xj0 = x0[j];
                a00 = fmaf(s0, xj0, a00);
                a01 = fmaf(s1, xj0, a01);
                a02 = fmaf(s2, xj0, a02);
                a03 = fmaf(s3, xj0, a03);
                // node 1: 4 independent chains
                float t0c = fmaf(A.x, x1[0], u);
                float t1c = A.y * x1[1];
                float t2c = A.z * x1[2];
                float t3c = A.w * x1[3];
                t0c = fmaf(B.x,  x1[4],  t0c);
                t1c = fmaf(B.y,  x1[5],  t1c);
                t2c = fmaf(B.z,  x1[6],  t2c);
                t3c = fmaf(B.w,  x1[7],  t3c);
                t0c = fmaf(C4.x, x1[8],  t0c);
                t1c = fmaf(C4.y, x1[9],  t1c);
                t2c = fmaf(C4.z, x1[10], t2c);
                t3c = fmaf(C4.w, x1[11], t3c);
                t0c = fmaf(D4.x, x1[12], t0c);
                t1c = fmaf(D4.y, x1[13], t1c);
                t2c = fmaf(D4.z, x1[14], t2c);
                t3c = fmaf(D4.w, x1[15], t3c);
                const float xj1 = x1[j];
                a10 = fmaf(t0c, xj1, a10);
                a11 = fmaf(t1c, xj1, a11);
                a12 = fmaf(t2c, xj1, a12);
                a13 = fmaf(t3c, xj1, a13);
            }
            const float u1v = sUW1[i];
            const float acc0 = ((a00 + a01) + (a02 + a03)) + u1v;
            const float acc1 = ((a10 + a11) + (a12 + a13)) + u1v;
            yo0 = fmaf(acc0, x0[i], yo0);
            yo1 = fmaf(acc1, x1[i], yo1);
        }
        g_y[((size_t)b0 * 128 + c) * 4 + oc] = yo0;
        if (v1) g_y[((size_t)b1 * 128 + c) * 4 + oc] = yo1;
    }
}

// ---------------- kernel 5: irrep-wise linear + flatten ----------------
// grid 128 blocks, 128 threads, 8 nodes per block
__global__ void k_lin(const float* __restrict__ wl, float* __restrict__ out) {
    __shared__ float sY[8 * 512]; // 16KB
    const int tid = threadIdx.x;
    const int b0 = blockIdx.x * 8;
#pragma unroll
    for (int it = 0; it < 8; it++)
        ((float4*)sY)[tid + it * 128] = ((const float4*)(g_y + (size_t)b0 * 512))[tid + it * 128];
    __syncthreads();

    const int n = tid;
    float acc[8][4];
#pragma unroll
    for (int bb = 0; bb < 8; bb++)
#pragma unroll
        for (int o = 0; o < 4; o++) acc[bb][o] = 0.f;

    for (int cc = 0; cc < 128; cc++) {
        float w0  = wl[cc * 128 + n];           // w_lin[0][cc][n]
        float w1v = wl[16384 + cc * 128 + n];   // w_lin[1][cc][n]
#pragma unroll
        for (int bb = 0; bb < 8; bb++) {
            float4 yv = *(const float4*)(sY + bb * 512 + cc * 4);
            acc[bb][0] = fmaf(yv.x, w0,  acc[bb][0]);
            acc[bb][1] = fmaf(yv.y, w1v, acc[bb][1]);
            acc[bb][2] = fmaf(yv.z, w1v, acc[bb][2]);
            acc[bb][3] = fmaf(yv.w, w1v, acc[bb][3]);
        }
    }
    const float scale = 0.08838834764831843f; // 1/sqrt(128)
#pragma unroll
    for (int bb = 0; bb < 8; bb++) {
        float* op = out + (size_t)(b0 + bb) * 512;
        op[n]               = acc[bb][0] * scale;
        op[128 + n * 3 + 0] = acc[bb][1] * scale;
        op[128 + n * 3 + 1] = acc[bb][2] * scale;
        op[128 + n * 3 + 2] = acc[bb][3] * scale;
    }
}

// ---------------- launch ----------------
extern "C" void kernel_launch(void* const* d_in, const int* in_sizes, int n_in,
                              void* d_out, int out_size) {
    const float* node_feats = (const float*)d_in[0];
    const float* u3_0 = (const float*)d_in[1];
    const float* u3_1 = (const float*)d_in[2];
    const float* u2_0 = (const float*)d_in[3];
    const float* u2_1 = (const float*)d_in[4];
    const float* u1_0 = (const float*)d_in[5];
    const float* u1_1 = (const float*)d_in[6];
    const float* w3   = (const float*)d_in[7];
    const float* w2   = (const float*)d_in[8];
    const float* w1   = (const float*)d_in[9];
    const float* wlin = (const float*)d_in[10];
    const int*   spec = (const int*)d_in[11];
    float* out = (float*)d_out;

    k_uw3<<<dim3(128, 2, 4), 128>>>(u3_0, u3_1, w3);
    k_uw21<<<512, 128>>>(u2_0, u2_1, u1_0, u1_1, w2, w1);
    k_sort<<<1, 1024>>>(spec);
    k_main2<<<dim3(128, 4, 4), TM2>>>(node_feats);
    k_lin<<<128, 128>>>(wlin, out);
}

// round 5
// speedup vs baseline: 1.5980x; 1.5980x over previous
#include <cuda_runtime.h>

#define BN 1024
#define CN 128
#define DN 16
#define SN 4
#define K3C 23
#define K2C 5
#define K1C 2

#define NM3 816   // C(18,3) sorted triples i>=j>=l
#define NM2 136   // C(17,2) sorted pairs  i>=j
#define STREAM_LEN (NM3*4 + NM2*4 + 16*4)  // 3872 floats per (e,c)

// ---------------- scratch ----------------
__device__ float g_us3[NM3 * 4 * K3C];                 // [m3][oc][k]
__device__ float g_us2[NM2 * 4 * K2C];                 // [m2][oc][k]
__device__ float g_stream[(size_t)SN * CN * STREAM_LEN]; // [e][c][3872]
__device__ int   g_sorted[BN];
__device__ int   g_off[SN + 1];
__device__ float g_y[(size_t)BN * CN * 4];             // [b][c][oc]

// ---------------- presym: u3 -> symmetric monomial basis ----------------
// grid 7, 128 threads (one per m3)
__global__ void k_presym3(const float* __restrict__ u3_0, const float* __restrict__ u3_1) {
    int m = blockIdx.x * 128 + threadIdx.x;
    if (m >= NM3) return;
    int i = 0;
    while ((i + 1) * (i + 2) * (i + 3) / 6 <= m) i++;
    int r = m - i * (i + 1) * (i + 2) / 6;
    int j = 0;
    while ((j + 1) * (j + 2) / 2 <= r) j++;
    int l = r - j * (j + 1) / 2;

    int P[6][3] = {{i,j,l},{i,l,j},{j,i,l},{j,l,i},{l,i,j},{l,j,i}};
    for (int oc = 0; oc < 4; oc++) {
        for (int k = 0; k < K3C; k++) {
            float s = 0.f;
            for (int p = 0; p < 6; p++) {
                bool dup = false;
                for (int q = 0; q < p; q++)
                    if (P[p][0] == P[q][0] && P[p][1] == P[q][1] && P[p][2] == P[q][2]) dup = true;
                if (dup) continue;
                int a = P[p][0], b = P[p][1], d = P[p][2];
                float v = (oc == 0)
                    ? u3_0[(((a * 16 + b) * 16) + d) * K3C + k]
                    : u3_1[((((oc - 1) * 16 + a) * 16 + b) * 16 + d) * K3C + k];
                s += v;
            }
            g_us3[(m * 4 + oc) * K3C + k] = s;
        }
    }
}

// 1 block, 160 threads (one per m2)
__global__ void k_presym2(const float* __restrict__ u2_0, const float* __restrict__ u2_1) {
    int m = threadIdx.x;
    if (m >= NM2) return;
    int i = 0;
    while ((i + 1) * (i + 2) / 2 <= m) i++;
    int j = m - i * (i + 1) / 2;
    for (int oc = 0; oc < 4; oc++) {
        for (int k = 0; k < K2C; k++) {
            float s = (oc == 0) ? u2_0[(i * 16 + j) * K2C + k]
                                : u2_1[(((oc - 1) * 16 + i) * 16 + j) * K2C + k];
            if (i != j)
                s += (oc == 0) ? u2_0[(j * 16 + i) * K2C + k]
                               : u2_1[(((oc - 1) * 16 + j) * 16 + i) * K2C + k];
            g_us2[(m * 4 + oc) * K2C + k] = s;
        }
    }
}

// ---------------- fold corr-3 stream: S3[e,c,m,oc] = sum_k us3[m,oc,k]*w3[br,e,k,c] ----------------
// grid (13 m-tiles of 64, 4 species), 128 threads (= c)
__global__ void k_fold3(const float* __restrict__ w3) {
    __shared__ float s_us3[64 * 4 * K3C];  // 5888 floats
    __shared__ float s_w3[2 * K3C * 128];  // 5888 floats
    const int tid = threadIdx.x;
    const int mt = blockIdx.x * 64;
    const int e = blockIdx.y;
    const int nm = (NM3 - mt < 64) ? (NM3 - mt) : 64;

    for (int idx = tid; idx < 2 * K3C * 128; idx += 128) {
        int br = idx / (K3C * 128);
        int rem = idx - br * (K3C * 128);
        int k = rem >> 7, cc = rem & 127;
        s_w3[idx] = w3[(((size_t)(br * 4 + e) * K3C + k) * 128) + cc];
    }
    for (int idx = tid; idx < nm * 4 * K3C; idx += 128)
        s_us3[idx] = g_us3[mt * 4 * K3C + idx];
    __syncthreads();

    const int c = tid;
    float* outp = g_stream + ((size_t)(e * 128 + c)) * STREAM_LEN;
    for (int mm = 0; mm < nm; mm++) {
        float a0 = 0.f, a1 = 0.f, a2 = 0.f, a3 = 0.f;
        const float* u0 = s_us3 + (mm * 4 + 0) * K3C;
        const float* u1p = s_us3 + (mm * 4 + 1) * K3C;
        const float* u2p = s_us3 + (mm * 4 + 2) * K3C;
        const float* u3p = s_us3 + (mm * 4 + 3) * K3C;
#pragma unroll
        for (int k = 0; k < K3C; k++) {
            float w0 = s_w3[k * 128 + c];
            float w1v = s_w3[K3C * 128 + k * 128 + c];
            a0 = fmaf(u0[k], w0, a0);
            a1 = fmaf(u1p[k], w1v, a1);
            a2 = fmaf(u2p[k], w1v, a2);
            a3 = fmaf(u3p[k], w1v, a3);
        }
        *(float4*)(outp + (size_t)(mt + mm) * 4) = make_float4(a0, a1, a2, a3);
    }
}

// ---------------- fold corr-2 / corr-1 streams ----------------
// grid 4 (e), 128 threads (= c)
__global__ void k_fold21(const float* __restrict__ w2, const float* __restrict__ w1,
                         const float* __restrict__ u1_0, const float* __restrict__ u1_1) {
    __shared__ float s_us2[NM2 * 4 * K2C];  // 2720
    __shared__ float s_w2[2 * K2C * 128];   // 1280
    __shared__ float s_w1[2 * K1C * 128];   // 512
    __shared__ float s_u1[4 * 16 * K1C];    // 128
    const int tid = threadIdx.x;
    const int e = blockIdx.x;

    for (int idx = tid; idx < NM2 * 4 * K2C; idx += 128) s_us2[idx] = g_us2[idx];
    for (int idx = tid; idx < 2 * K2C * 128; idx += 128) {
        int br = idx / (K2C * 128);
        int rem = idx - br * (K2C * 128);
        int k = rem >> 7, cc = rem & 127;
        s_w2[idx] = w2[(((size_t)(br * 4 + e) * K2C + k) * 128) + cc];
    }
    for (int idx = tid; idx < 2 * K1C * 128; idx += 128) {
        int br = idx / (K1C * 128);
        int rem = idx - br * (K1C * 128);
        int k = rem >> 7, cc = rem & 127;
        s_w1[idx] = w1[(((size_t)(br * 4 + e) * K1C + k) * 128) + cc];
    }
    for (int idx = tid; idx < 4 * 16 * K1C; idx += 128) {
        int oc = idx / (16 * K1C);
        int rem = idx - oc * (16 * K1C);
        int i = rem / K1C, k = rem % K1C;
        s_u1[idx] = (oc == 0) ? u1_0[i * K1C + k]
                              : u1_1[((oc - 1) * 16 + i) * K1C + k];
    }
    __syncthreads();

    const int c = tid;
    float* outp = g_stream + ((size_t)(e * 128 + c)) * STREAM_LEN;
    for (int m = 0; m < NM2; m++) {
        float a0 = 0.f, a1 = 0.f, a2 = 0.f, a3 = 0.f;
#pragma unroll
        for (int k = 0; k < K2C; k++) {
            float w0 = s_w2[k * 128 + c];
            float w1v = s_w2[K2C * 128 + k * 128 + c];
            a0 = fmaf(s_us2[(m * 4 + 0) * K2C + k], w0, a0);
            a1 = fmaf(s_us2[(m * 4 + 1) * K2C + k], w1v, a1);
            a2 = fmaf(s_us2[(m * 4 + 2) * K2C + k], w1v, a2);
            a3 = fmaf(s_us2[(m * 4 + 3) * K2C + k], w1v, a3);
        }
        *(float4*)(outp + NM3 * 4 + (size_t)m * 4) = make_float4(a0, a1, a2, a3);
    }
    for (int i = 0; i < 16; i++) {
        float a0 = 0.f, a1 = 0.f, a2 = 0.f, a3 = 0.f;
#pragma unroll
        for (int k = 0; k < K1C; k++) {
            float w0 = s_w1[k * 128 + c];
            float w1v = s_w1[K1C * 128 + k * 128 + c];
            a0 = fmaf(s_u1[(0 * 16 + i) * K1C + k], w0, a0);
            a1 = fmaf(s_u1[(1 * 16 + i) * K1C + k], w1v, a1);
            a2 = fmaf(s_u1[(2 * 16 + i) * K1C + k], w1v, a2);
            a3 = fmaf(s_u1[(3 * 16 + i) * K1C + k], w1v, a3);
        }
        *(float4*)(outp + NM3 * 4 + NM2 * 4 + (size_t)i * 4) = make_float4(a0, a1, a2, a3);
    }
}

// ---------------- counting sort by species ----------------
__global__ void k_sort(const int* __restrict__ species) {
    __shared__ int cnt[SN], cur[SN], off[SN + 1];
    const int tid = threadIdx.x; // 1024
    if (tid < SN) { cnt[tid] = 0; cur[tid] = 0; }
    __syncthreads();
    int s = species[tid];
    atomicAdd(&cnt[s], 1);
    __syncthreads();
    if (tid == 0) {
        off[0] = 0;
        for (int e = 0; e < SN; e++) off[e + 1] = off[e] + cnt[e];
        for (int e = 0; e <= SN; e++) g_off[e] = off[e];
    }
    __syncthreads();
    int pos = off[s] + atomicAdd(&cur[s], 1);
    g_sorted[pos] = tid;
}

// ---------------- main: symmetric monomial evaluation ----------------
// grid (c=128, e=4), 128 threads, 2 nodes/thread, fully unrolled stream walk
#define TMS 128
__global__ __launch_bounds__(TMS, 4) void k_main_sym(const float* __restrict__ xg) {
    __shared__ __align__(16) float sC[STREAM_LEN]; // 15.5KB: [S3 816*4][S2 136*4][S1 16*4]
    const int c = blockIdx.x, e = blockIdx.y;
    const int tid = threadIdx.x;

    {
        const float4* gs = (const float4*)(g_stream + ((size_t)(e * 128 + c)) * STREAM_LEN);
        float4* s4 = (float4*)sC;
#pragma unroll
        for (int q = 0; q < 8; q++) {
            int idx = tid + q * TMS;
            if (idx < STREAM_LEN / 4) s4[idx] = gs[idx];
        }
    }
    const int lo = g_off[e], hi = g_off[e + 1];
    __syncthreads();

    const float4* p3 = (const float4*)sC;                 // 816 monomial coef4
    const float4* p2 = (const float4*)(sC + NM3 * 4);     // 136
    const float4* p1 = (const float4*)(sC + NM3 * 4 + NM2 * 4); // 16

    for (int base = lo; base < hi; base += 2 * TMS) {
        const int t0 = base + tid;
        if (t0 >= hi) break;
        const int t1 = t0 + TMS;
        const bool v1 = (t1 < hi);
        const int b0 = g_sorted[t0];
        const int b1 = v1 ? g_sorted[t1] : b0;

        float x0[16], x1[16];
        {
            const float4* q0 = (const float4*)(xg + ((size_t)b0 * 128 + c) * 16);
            const float4* q1 = (const float4*)(xg + ((size_t)b1 * 128 + c) * 16);
#pragma unroll
            for (int q = 0; q < 4; q++) {
                float4 a = q0[q];
                x0[4 * q + 0] = a.x; x0[4 * q + 1] = a.y; x0[4 * q + 2] = a.z; x0[4 * q + 3] = a.w;
                float4 b = q1[q];
                x1[4 * q + 0] = b.x; x1[4 * q + 1] = b.y; x1[4 * q + 2] = b.z; x1[4 * q + 3] = b.w;
            }
        }

        float y00 = 0.f, y01 = 0.f, y02 = 0.f, y03 = 0.f;
        float y10 = 0.f, y11 = 0.f, y12 = 0.f, y13 = 0.f;
        int m3 = 0, m2 = 0;
#pragma unroll
        for (int i = 0; i < 16; i++) {
            {
                const float4 c1 = p1[i];
                const float xi0 = x0[i], xi1 = x1[i];
                y00 = fmaf(c1.x, xi0, y00);
                y01 = fmaf(c1.y, xi0, y01);
                y02 = fmaf(c1.z, xi0, y02);
                y03 = fmaf(c1.w, xi0, y03);
                y10 = fmaf(c1.x, xi1, y10);
                y11 = fmaf(c1.y, xi1, y11);
                y12 = fmaf(c1.z, xi1, y12);
                y13 = fmaf(c1.w, xi1, y13);
            }
#pragma unroll
            for (int j = 0; j <= i; j++) {
                const float q0 = x0[i] * x0[j];
                const float q1 = x1[i] * x1[j];
                {
                    const float4 c2 = p2[m2]; m2++;
                    y00 = fmaf(c2.x, q0, y00);
                    y01 = fmaf(c2.y, q0, y01);
                    y02 = fmaf(c2.z, q0, y02);
                    y03 = fmaf(c2.w, q0, y03);
                    y10 = fmaf(c2.x, q1, y10);
                    y11 = fmaf(c2.y, q1, y11);
                    y12 = fmaf(c2.z, q1, y12);
                    y13 = fmaf(c2.w, q1, y13);
                }
#pragma unroll
                for (int l = 0; l <= j; l++) {
                    const float4 c3 = p3[m3]; m3++;
                    const float t0v = q0 * x0[l];
                    const float t1v = q1 * x1[l];
                    y00 = fmaf(c3.x, t0v, y00);
                    y01 = fmaf(c3.y, t0v, y01);
                    y02 = fmaf(c3.z, t0v, y02);
                    y03 = fmaf(c3.w, t0v, y03);
                    y10 = fmaf(c3.x, t1v, y10);
                    y11 = fmaf(c3.y, t1v, y11);
                    y12 = fmaf(c3.z, t1v, y12);
                    y13 = fmaf(c3.w, t1v, y13);
                }
            }
        }
        *(float4*)(g_y + ((size_t)b0 * 128 + c) * 4) = make_float4(y00, y01, y02, y03);
        if (v1)
            *(float4*)(g_y + ((size_t)b1 * 128 + c) * 4) = make_float4(y10, y11, y12, y13);
    }
}

// ---------------- irrep-wise linear + flatten ----------------
// grid 128 blocks, 128 threads, 8 nodes per block
__global__ void k_lin(const float* __restrict__ wl, float* __restrict__ out) {
    __shared__ float sY[8 * 512]; // 16KB
    const int tid = threadIdx.x;
    const int b0 = blockIdx.x * 8;
#pragma unroll
    for (int it = 0; it < 8; it++)
        ((float4*)sY)[tid + it * 128] = ((const float4*)(g_y + (size_t)b0 * 512))[tid + it * 128];
    __syncthreads();

    const int n = tid;
    float acc[8][4];
#pragma unroll
    for (int bb = 0; bb < 8; bb++)
#pragma unroll
        for (int o = 0; o < 4; o++) acc[bb][o] = 0.f;

    for (int cc = 0; cc < 128; cc++) {
        float w0  = wl[cc * 128 + n];
        float w1v = wl[16384 + cc * 128 + n];
#pragma unroll
        for (int bb = 0; bb < 8; bb++) {
            float4 yv = *(const float4*)(sY + bb * 512 + cc * 4);
            acc[bb][0] = fmaf(yv.x, w0,  acc[bb][0]);
            acc[bb][1] = fmaf(yv.y, w1v, acc[bb][1]);
            acc[bb][2] = fmaf(yv.z, w1v, acc[bb][2]);
            acc[bb][3] = fmaf(yv.w, w1v, acc[bb][3]);
        }
    }
    const float scale = 0.08838834764831843f; // 1/sqrt(128)
#pragma unroll
    for (int bb = 0; bb < 8; bb++) {
        float* op = out + (size_t)(b0 + bb) * 512;
        op[n]               = acc[bb][0] * scale;
        op[128 + n * 3 + 0] = acc[bb][1] * scale;
        op[128 + n * 3 + 1] = acc[bb][2] * scale;
        op[128 + n * 3 + 2] = acc[bb][3] * scale;
    }
}

// ---------------- launch ----------------
extern "C" void kernel_launch(void* const* d_in, const int* in_sizes, int n_in,
                              void* d_out, int out_size) {
    const float* node_feats = (const float*)d_in[0];
    const float* u3_0 = (const float*)d_in[1];
    const float* u3_1 = (const float*)d_in[2];
    const float* u2_0 = (const float*)d_in[3];
    const float* u2_1 = (const float*)d_in[4];
    const float* u1_0 = (const float*)d_in[5];
    const float* u1_1 = (const float*)d_in[6];
    const float* w3   = (const float*)d_in[7];
    const float* w2   = (const float*)d_in[8];
    const float* w1   = (const float*)d_in[9];
    const float* wlin = (const float*)d_in[10];
    const int*   spec = (const int*)d_in[11];
    float* out = (float*)d_out;

    k_presym3<<<7, 128>>>(u3_0, u3_1);
    k_presym2<<<1, 160>>>(u2_0, u2_1);
    k_sort<<<1, 1024>>>(spec);
    k_fold3<<<dim3(13, 4), 128>>>(w3);
    k_fold21<<<4, 128>>>(w2, w1, u1_0, u1_1);
    k_main_sym<<<dim3(128, 4), TMS>>>(node_feats);
    k_lin<<<128, 128>>>(wlin, out);
}